// round 7
// baseline (speedup 1.0000x reference)
#include <cuda_runtime.h>

#define T_STEPS 16
#define BLK 224
#define EPB 448            // batch elements per block (2 per thread)

using ull = unsigned long long;

union F2u { ull u; float2 f; };

__device__ __forceinline__ ull fma2(ull a, ull b, ull c) {
    ull d;
    asm("fma.rn.f32x2 %0, %1, %2, %3;" : "=l"(d) : "l"(a), "l"(b), "l"(c));
    return d;
}
__device__ __forceinline__ float hsum2(ull a, ull b) {
    ull s;
    asm("add.rn.f32x2 %0, %1, %2;" : "=l"(s) : "l"(a), "l"(b));
    F2u x; x.u = s;
    return x.f.x + x.f.y;
}

__device__ __forceinline__ float tanh_ap(float x) {
    float y; asm("tanh.approx.f32 %0, %1;" : "=f"(y) : "f"(x)); return y;
}
__device__ __forceinline__ float sigm(float x) {
    return fmaf(tanh_ap(0.5f * x), 0.5f, 0.5f);
}
__device__ __forceinline__ float softplus_(float x) {
    return fmaxf(x, 0.0f) + log1pf(__expf(-fabsf(x)));   // exact: sets rel_err
}

// shared-memory float offsets
#define OFF_WHH 0        // 12288  (192 x 64, row-major)
#define OFF_W1T 12288    // 2048   (transposed: [m*64+k])
#define OFF_GIW 14336    // 192 x float4 {wih0, wih1, bias(.z), bhh_n(.w)} = 768 floats
#define OFF_B1  15104    // 32
#define OFF_W2  15136    // 128    (32 x 4 row-major -> float4 per row)
#define OFF_B2  15264    // 4
#define WEIGHT_BYTES (15268 * 4)                  // 61072, 16B-aligned
#define SMEM_BYTES (WEIGHT_BYTES + 32 * EPB * 8)  // + hbuf (ull[32][EPB]) = 175760

__global__ void __launch_bounds__(BLK)
flow_kernel(const float* __restrict__ x, const float* __restrict__ z,
            const float* __restrict__ W_ih, const float* __restrict__ W_hh,
            const float* __restrict__ b_ih, const float* __restrict__ b_hh,
            const float* __restrict__ W1, const float* __restrict__ b1,
            const float* __restrict__ W2, const float* __restrict__ b2,
            float* __restrict__ out, int Btot)
{
    extern __shared__ unsigned char smem_raw[];
    float* sw = (float*)smem_raw;
    const int tid = threadIdx.x;

    // ---- stage weights into shared ----
    for (int i = tid; i < 12288; i += BLK) sw[OFF_WHH + i] = W_hh[i];
    for (int i = tid; i < 2048; i += BLK) {         // transpose W1 (64x32) -> [m][k]
        int m = i >> 6, k = i & 63;
        sw[OFF_W1T + i] = W1[k * 32 + m];
    }
    for (int j = tid; j < 192; j += BLK) {          // giw: wih pair + biases
        float bi = b_ih[j], bh = b_hh[j];
        float4 v;
        if (j < 128) v = make_float4(W_ih[2 * j], W_ih[2 * j + 1], bi + bh, 0.0f);
        else         v = make_float4(W_ih[2 * j], W_ih[2 * j + 1], bi, bh);
        *(float4*)(sw + OFF_GIW + j * 4) = v;
    }
    for (int i = tid; i < 128; i += BLK) sw[OFF_W2 + i] = W2[i];
    if (tid < 32) sw[OFF_B1 + tid] = b1[tid];
    if (tid < 4)  sw[OFF_B2 + tid] = b2[tid];
    __syncthreads();

    ull* hbuf = (ull*)(smem_raw + WEIGHT_BYTES);   // [32][EPB] per-element h scratch

    const int b0 = blockIdx.x * EPB + tid;          // element A
    const int b1r = b0 + BLK;                       // element B (may exceed Btot last block)
    const bool vB = (b1r < Btot);
    const int b1i = vB ? b1r : b0;                  // clamp for loads

    // h = z for both elements (packed pairs, register-resident)
    ull ha[32], hb[32];
    const ull* za = (const ull*)(z + (size_t)b0 * 64);
    const ull* zbv = (const ull*)(z + (size_t)b1i * 64);
    #pragma unroll
    for (int k = 0; k < 32; ++k) { ha[k] = za[k]; hb[k] = zbv[k]; }

    const float2* xA = (const float2*)(x + (size_t)b0  * (T_STEPS * 2));
    const float2* xB = (const float2*)(x + (size_t)b1i * (T_STEPS * 2));
    float2*       yA = (float2*)(out + (size_t)b0  * (T_STEPS * 2));
    float2*       yB = (float2*)(out + (size_t)b1r * (T_STEPS * 2));

    const ulonglong2* whh2 = (const ulonglong2*)(sw + OFF_WHH);  // row j at j*16
    const float4* giw = (const float4*)(sw + OFF_GIW);
    const ulonglong2* w1t2 = (const ulonglong2*)(sw + OFF_W1T);  // row m at m*16
    const float4* w2v = (const float4*)(sw + OFF_W2);
    const float* b1s = sw + OFF_B1;
    const float* b2s = sw + OFF_B2;
    const float bb20 = b2s[0], bb21 = b2s[1], bb22 = b2s[2], bb23 = b2s[3];

    float yA0 = 0.f, yA1 = 0.f, yB0 = 0.f, yB1 = 0.f;   // y_{t-1}
    float pA0 = 1.f, pA1 = 1.f, pB0 = 1.f, pB1 = 1.f;   // running scale products

    // gate body for one (j, half) — hold comes from REGISTERS (ha/hb halves)
#define GATE_BODY(HX, YP0, YP1, AR0, AR1, AZ0, AZ1, AN0, AN1, J, HALF, HSPTR)          \
    {                                                                                   \
        float4 wgr = giw[(J)];                                                          \
        float4 wgz = giw[64 + (J)];                                                     \
        float4 wgn = giw[128 + (J)];                                                    \
        float hr = hsum2(AR0, AR1);                                                     \
        float hz = hsum2(AZ0, AZ1);                                                     \
        float hn = hsum2(AN0, AN1) + wgn.w;                                             \
        float r = sigm(fmaf(YP1, wgr.y, fmaf(YP0, wgr.x, wgr.z)) + hr);                 \
        float u = sigm(fmaf(YP1, wgz.y, fmaf(YP0, wgz.x, wgz.z)) + hz);                 \
        float gn = fmaf(YP1, wgn.y, fmaf(YP0, wgn.x, wgn.z));                           \
        float n = tanh_ap(fmaf(r, hn, gn));                                             \
        F2u hv_; hv_.u = HX[(J) >> 1];                                                  \
        float hold = (HALF) ? hv_.f.y : hv_.f.x;                                        \
        (HSPTR)[(HALF)] = fmaf(u, hold - n, n);                                         \
    }

    #pragma unroll 1
    for (int t = 0; t < T_STEPS; ++t) {
        float2 xa = xA[t];
        float2 xbv = xB[t];

        // ---- GRU: gh = h @ W_hh^T (+ biases), fused gates, j unrolled x2 ----
        #pragma unroll 1
        for (int jp = 0; jp < 32; ++jp) {
            const int j0 = 2 * jp;
            const ulonglong2* wr0 = whh2 + j0 * 16;          // rows j0, j0+1
            float* hsA = (float*)(hbuf + jp * EPB + tid);
            float* hsB = (float*)(hbuf + jp * EPB + BLK + tid);

            // -------- j0 (even half) --------
            {
                const ulonglong2* wzp = wr0 + 1024;
                const ulonglong2* wn = wr0 + 2048;
                ull arA0 = 0, arA1 = 0, azA0 = 0, azA1 = 0, anA0 = 0, anA1 = 0;
                ull arB0 = 0, arB1 = 0, azB0 = 0, azB1 = 0, anB0 = 0, anB1 = 0;
                #pragma unroll
                for (int kk = 0; kk < 16; ++kk) {
                    ulonglong2 wa = wr0[kk];
                    arA0 = fma2(ha[2 * kk], wa.x, arA0); arA1 = fma2(ha[2 * kk + 1], wa.y, arA1);
                    arB0 = fma2(hb[2 * kk], wa.x, arB0); arB1 = fma2(hb[2 * kk + 1], wa.y, arB1);
                    ulonglong2 wb = wzp[kk];
                    azA0 = fma2(ha[2 * kk], wb.x, azA0); azA1 = fma2(ha[2 * kk + 1], wb.y, azA1);
                    azB0 = fma2(hb[2 * kk], wb.x, azB0); azB1 = fma2(hb[2 * kk + 1], wb.y, azB1);
                    ulonglong2 wc = wn[kk];
                    anA0 = fma2(ha[2 * kk], wc.x, anA0); anA1 = fma2(ha[2 * kk + 1], wc.y, anA1);
                    anB0 = fma2(hb[2 * kk], wc.x, anB0); anB1 = fma2(hb[2 * kk + 1], wc.y, anB1);
                }
                GATE_BODY(ha, yA0, yA1, arA0, arA1, azA0, azA1, anA0, anA1, j0, 0, hsA);
                GATE_BODY(hb, yB0, yB1, arB0, arB1, azB0, azB1, anB0, anB1, j0, 0, hsB);
            }
            // -------- j0+1 (odd half) --------
            {
                const ulonglong2* wr1 = wr0 + 16;
                const ulonglong2* wzp = wr1 + 1024;
                const ulonglong2* wn = wr1 + 2048;
                ull arA0 = 0, arA1 = 0, azA0 = 0, azA1 = 0, anA0 = 0, anA1 = 0;
                ull arB0 = 0, arB1 = 0, azB0 = 0, azB1 = 0, anB0 = 0, anB1 = 0;
                #pragma unroll
                for (int kk = 0; kk < 16; ++kk) {
                    ulonglong2 wa = wr1[kk];
                    arA0 = fma2(ha[2 * kk], wa.x, arA0); arA1 = fma2(ha[2 * kk + 1], wa.y, arA1);
                    arB0 = fma2(hb[2 * kk], wa.x, arB0); arB1 = fma2(hb[2 * kk + 1], wa.y, arB1);
                    ulonglong2 wb = wzp[kk];
                    azA0 = fma2(ha[2 * kk], wb.x, azA0); azA1 = fma2(ha[2 * kk + 1], wb.y, azA1);
                    azB0 = fma2(hb[2 * kk], wb.x, azB0); azB1 = fma2(hb[2 * kk + 1], wb.y, azB1);
                    ulonglong2 wc = wn[kk];
                    anA0 = fma2(ha[2 * kk], wc.x, anA0); anA1 = fma2(ha[2 * kk + 1], wc.y, anA1);
                    anB0 = fma2(hb[2 * kk], wc.x, anB0); anB1 = fma2(hb[2 * kk + 1], wc.y, anB1);
                }
                GATE_BODY(ha, yA0, yA1, arA0, arA1, azA0, azA1, anA0, anA1, j0 + 1, 1, hsA);
                GATE_BODY(hb, yB0, yB1, arB0, arB1, azB0, azB1, anB0, anB1, j0 + 1, 1, hsB);
            }
        }

        // reload h (now h_new) into registers
        #pragma unroll
        for (int k = 0; k < 32; ++k) {
            ha[k] = hbuf[k * EPB + tid];
            hb[k] = hbuf[k * EPB + BLK + tid];
        }

        // ---- MLP: ls = relu(h@W1 + b1) @ W2 + b2, unroll x2 for ILP ----
        float lsA0 = bb20, lsA1 = bb21, lsA2 = bb22, lsA3 = bb23;
        float lsB0 = bb20, lsB1 = bb21, lsB2 = bb22, lsB3 = bb23;
        #pragma unroll 2
        for (int m = 0; m < 32; ++m) {
            const ulonglong2* wm = w1t2 + m * 16;
            ull aA0 = 0, aA1 = 0, aB0 = 0, aB1 = 0;
            #pragma unroll
            for (int kk = 0; kk < 16; ++kk) {
                ulonglong2 w = wm[kk];
                aA0 = fma2(ha[2 * kk], w.x, aA0);
                aA1 = fma2(ha[2 * kk + 1], w.y, aA1);
                aB0 = fma2(hb[2 * kk], w.x, aB0);
                aB1 = fma2(hb[2 * kk + 1], w.y, aB1);
            }
            float hidA = fmaxf(hsum2(aA0, aA1) + b1s[m], 0.0f);
            float hidB = fmaxf(hsum2(aB0, aB1) + b1s[m], 0.0f);
            float4 wv = w2v[m];
            lsA0 = fmaf(hidA, wv.x, lsA0);
            lsA1 = fmaf(hidA, wv.y, lsA1);
            lsA2 = fmaf(hidA, wv.z, lsA2);
            lsA3 = fmaf(hidA, wv.w, lsA3);
            lsB0 = fmaf(hidB, wv.x, lsB0);
            lsB1 = fmaf(hidB, wv.y, lsB1);
            lsB2 = fmaf(hidB, wv.z, lsB2);
            lsB3 = fmaf(hidB, wv.w, lsB3);
        }

        // element A head
        {
            float s0 = softplus_(lsA2) + 0.001f;
            float s1 = softplus_(lsA3) + 0.001f;
            float y0 = yA0 + lsA0 + s0 * xa.x;
            float y1 = yA1 + lsA1 + s1 * xa.y;
            yA[t] = make_float2(y0, y1);
            pA0 *= s0; pA1 *= s1;
            yA0 = y0; yA1 = y1;
        }
        // element B head
        {
            float s0 = softplus_(lsB2) + 0.001f;
            float s1 = softplus_(lsB3) + 0.001f;
            float y0 = yB0 + lsB0 + s0 * xbv.x;
            float y1 = yB1 + lsB1 + s1 * xbv.y;
            if (vB) yB[t] = make_float2(y0, y1);
            pB0 *= s0; pB1 *= s1;
            yB0 = y0; yB1 = y1;
        }
    }

    // logabsdet (match reference: log|prod over T| summed over D)
    out[(size_t)Btot * (T_STEPS * 2) + b0] = logf(fabsf(pA0)) + logf(fabsf(pA1));
    if (vB)
        out[(size_t)Btot * (T_STEPS * 2) + b1r] = logf(fabsf(pB0)) + logf(fabsf(pB1));
}

extern "C" void kernel_launch(void* const* d_in, const int* in_sizes, int n_in,
                              void* d_out, int out_size)
{
    const float* x    = (const float*)d_in[0];
    const float* z    = (const float*)d_in[1];
    const float* W_ih = (const float*)d_in[2];
    const float* W_hh = (const float*)d_in[3];
    const float* b_ih = (const float*)d_in[4];
    const float* b_hh = (const float*)d_in[5];
    const float* W1   = (const float*)d_in[6];
    const float* b1   = (const float*)d_in[7];
    const float* W2   = (const float*)d_in[8];
    const float* b2   = (const float*)d_in[9];

    int B = in_sizes[1] / 64;   // z is (B, 64)
    int grid = (B + EPB - 1) / EPB;   // 293 for B=131072 -> waves 148+145 (99% balance)

    cudaFuncSetAttribute(flow_kernel, cudaFuncAttributeMaxDynamicSharedMemorySize, SMEM_BYTES);

    flow_kernel<<<grid, BLK, SMEM_BYTES>>>(
        x, z, W_ih, W_hh, b_ih, b_hh, W1, b1, W2, b2, (float*)d_out, B);
}

// round 8
// speedup vs baseline: 1.1359x; 1.1359x over previous
#include <cuda_runtime.h>

#define T_STEPS 16
#define BLK 224
#define EPB 448            // batch elements per block (2 per thread)

using ull = unsigned long long;

union F2u { ull u; float2 f; };

__device__ __forceinline__ ull fma2(ull a, ull b, ull c) {
    ull d;
    asm("fma.rn.f32x2 %0, %1, %2, %3;" : "=l"(d) : "l"(a), "l"(b), "l"(c));
    return d;
}
__device__ __forceinline__ float hsum1(ull a) {
    F2u x; x.u = a;
    return x.f.x + x.f.y;
}

__device__ __forceinline__ float tanh_ap(float x) {
    float y; asm("tanh.approx.f32 %0, %1;" : "=f"(y) : "f"(x)); return y;
}
__device__ __forceinline__ float sigm(float x) {
    return fmaf(tanh_ap(0.5f * x), 0.5f, 0.5f);
}
__device__ __forceinline__ float softplus_(float x) {
    return fmaxf(x, 0.0f) + log1pf(__expf(-fabsf(x)));   // exact: sets rel_err
}

// shared-memory float offsets
#define OFF_WHH 0        // 12288  (192 x 64, row-major)
#define OFF_W1T 12288    // 2048   (transposed: [m*64+k])
#define OFF_GIW 14336    // 192 x float4 {wih0, wih1, bias(.z), bhh_n(.w)} = 768 floats
#define OFF_B1  15104    // 32
#define OFF_W2  15136    // 128    (32 x 4 row-major -> float4 per row)
#define OFF_B2  15264    // 4
#define WEIGHT_BYTES (15268 * 4)                  // 61072, 16B-aligned
#define SMEM_BYTES (WEIGHT_BYTES + 32 * EPB * 8)  // + hbuf (ull[32][EPB]) = 175760

__global__ void __launch_bounds__(BLK)
flow_kernel(const float* __restrict__ x, const float* __restrict__ z,
            const float* __restrict__ W_ih, const float* __restrict__ W_hh,
            const float* __restrict__ b_ih, const float* __restrict__ b_hh,
            const float* __restrict__ W1, const float* __restrict__ b1,
            const float* __restrict__ W2, const float* __restrict__ b2,
            float* __restrict__ out, int Btot)
{
    extern __shared__ unsigned char smem_raw[];
    float* sw = (float*)smem_raw;
    const int tid = threadIdx.x;

    // ---- stage weights into shared ----
    for (int i = tid; i < 12288; i += BLK) sw[OFF_WHH + i] = W_hh[i];
    for (int i = tid; i < 2048; i += BLK) {         // transpose W1 (64x32) -> [m][k]
        int m = i >> 6, k = i & 63;
        sw[OFF_W1T + i] = W1[k * 32 + m];
    }
    for (int j = tid; j < 192; j += BLK) {          // giw: wih pair + biases
        float bi = b_ih[j], bh = b_hh[j];
        float4 v;
        if (j < 128) v = make_float4(W_ih[2 * j], W_ih[2 * j + 1], bi + bh, 0.0f);
        else         v = make_float4(W_ih[2 * j], W_ih[2 * j + 1], bi, bh);
        *(float4*)(sw + OFF_GIW + j * 4) = v;
    }
    for (int i = tid; i < 128; i += BLK) sw[OFF_W2 + i] = W2[i];
    if (tid < 32) sw[OFF_B1 + tid] = b1[tid];
    if (tid < 4)  sw[OFF_B2 + tid] = b2[tid];
    __syncthreads();

    ull* hbuf = (ull*)(smem_raw + WEIGHT_BYTES);   // [32][EPB] per-element h scratch

    const int b0 = blockIdx.x * EPB + tid;          // element A
    const int b1r = b0 + BLK;                       // element B (may exceed Btot last block)
    const bool vB = (b1r < Btot);
    const int b1i = vB ? b1r : b0;                  // clamp for loads

    // h = z for both elements (packed pairs, register-resident)
    ull ha[32], hb[32];
    const ull* za = (const ull*)(z + (size_t)b0 * 64);
    const ull* zbv = (const ull*)(z + (size_t)b1i * 64);
    #pragma unroll
    for (int k = 0; k < 32; ++k) {
        ha[k] = za[k];  hbuf[k * EPB + tid] = ha[k];
        hb[k] = zbv[k]; hbuf[k * EPB + BLK + tid] = hb[k];
    }

    const float2* xA = (const float2*)(x + (size_t)b0  * (T_STEPS * 2));
    const float2* xB = (const float2*)(x + (size_t)b1i * (T_STEPS * 2));
    float2*       yA = (float2*)(out + (size_t)b0  * (T_STEPS * 2));
    float2*       yB = (float2*)(out + (size_t)b1r * (T_STEPS * 2));

    const ulonglong2* whh2 = (const ulonglong2*)(sw + OFF_WHH);  // row j at j*16
    const float4* giw = (const float4*)(sw + OFF_GIW);
    const ulonglong2* w1t2 = (const ulonglong2*)(sw + OFF_W1T);  // row m at m*16
    const float4* w2v = (const float4*)(sw + OFF_W2);
    const float* b1s = sw + OFF_B1;
    const float* b2s = sw + OFF_B2;
    const float bb20 = b2s[0], bb21 = b2s[1], bb22 = b2s[2], bb23 = b2s[3];

    float yA0 = 0.f, yA1 = 0.f, yB0 = 0.f, yB1 = 0.f;   // y_{t-1}
    float pA0 = 1.f, pA1 = 1.f, pB0 = 1.f, pB1 = 1.f;   // running scale products

    #pragma unroll 1
    for (int t = 0; t < T_STEPS; ++t) {
        float2 xa = xA[t];
        float2 xbv = xB[t];

        // ---- GRU: gh = h @ W_hh^T (+ biases), fused gates ----
        #pragma unroll 2
        for (int j = 0; j < 64; ++j) {
            // top-prefetch: giw rows + hold values (off the gate-tail critical path)
            const float4 wgr = giw[j];
            const float4 wgz = giw[64 + j];
            const float4 wgn = giw[128 + j];
            float* hs = (float*)((char*)hbuf + (size_t)(j >> 1) * (EPB * 8) + ((j & 1) << 2));
            const float holdA = hs[tid * 2];
            const float holdB = hs[(BLK + tid) * 2];

            const ulonglong2* wr = whh2 + j * 16;
            ull arA = 0, azA = 0, anA = 0;
            ull arB = 0, azB = 0, anB = 0;
            #pragma unroll
            for (int kk = 0; kk < 16; ++kk) {
                ulonglong2 wa = wr[kk];
                arA = fma2(ha[2 * kk], wa.x, arA); arA = fma2(ha[2 * kk + 1], wa.y, arA);
                arB = fma2(hb[2 * kk], wa.x, arB); arB = fma2(hb[2 * kk + 1], wa.y, arB);
                ulonglong2 wb = wr[1024 + kk];     // row 64+j
                azA = fma2(ha[2 * kk], wb.x, azA); azA = fma2(ha[2 * kk + 1], wb.y, azA);
                azB = fma2(hb[2 * kk], wb.x, azB); azB = fma2(hb[2 * kk + 1], wb.y, azB);
                ulonglong2 wc = wr[2048 + kk];     // row 128+j
                anA = fma2(ha[2 * kk], wc.x, anA); anA = fma2(ha[2 * kk + 1], wc.y, anA);
                anB = fma2(hb[2 * kk], wc.x, anB); anB = fma2(hb[2 * kk + 1], wc.y, anB);
            }
            // element A tail
            {
                float r = sigm(fmaf(yA1, wgr.y, fmaf(yA0, wgr.x, wgr.z)) + hsum1(arA));
                float u = sigm(fmaf(yA1, wgz.y, fmaf(yA0, wgz.x, wgz.z)) + hsum1(azA));
                float hn = hsum1(anA) + wgn.w;
                float gn = fmaf(yA1, wgn.y, fmaf(yA0, wgn.x, wgn.z));
                float n = tanh_ap(fmaf(r, hn, gn));
                hs[tid * 2] = fmaf(u, holdA - n, n);
            }
            // element B tail
            {
                float r = sigm(fmaf(yB1, wgr.y, fmaf(yB0, wgr.x, wgr.z)) + hsum1(arB));
                float u = sigm(fmaf(yB1, wgz.y, fmaf(yB0, wgz.x, wgz.z)) + hsum1(azB));
                float hn = hsum1(anB) + wgn.w;
                float gn = fmaf(yB1, wgn.y, fmaf(yB0, wgn.x, wgn.z));
                float n = tanh_ap(fmaf(r, hn, gn));
                hs[(BLK + tid) * 2] = fmaf(u, holdB - n, n);
            }
        }

        // reload h (now h_new) into registers
        #pragma unroll
        for (int k = 0; k < 32; ++k) {
            ha[k] = hbuf[k * EPB + tid];
            hb[k] = hbuf[k * EPB + BLK + tid];
        }

        // ---- MLP: ls = relu(h@W1 + b1) @ W2 + b2 ----
        float lsA0 = bb20, lsA1 = bb21, lsA2 = bb22, lsA3 = bb23;
        float lsB0 = bb20, lsB1 = bb21, lsB2 = bb22, lsB3 = bb23;
        #pragma unroll 2
        for (int m = 0; m < 32; ++m) {
            const ulonglong2* wm = w1t2 + m * 16;
            ull aA = 0, aB = 0;
            #pragma unroll
            for (int kk = 0; kk < 16; ++kk) {
                ulonglong2 w = wm[kk];
                aA = fma2(ha[2 * kk], w.x, aA); aA = fma2(ha[2 * kk + 1], w.y, aA);
                aB = fma2(hb[2 * kk], w.x, aB); aB = fma2(hb[2 * kk + 1], w.y, aB);
            }
            float hidA = fmaxf(hsum1(aA) + b1s[m], 0.0f);
            float hidB = fmaxf(hsum1(aB) + b1s[m], 0.0f);
            float4 wv = w2v[m];
            lsA0 = fmaf(hidA, wv.x, lsA0);
            lsA1 = fmaf(hidA, wv.y, lsA1);
            lsA2 = fmaf(hidA, wv.z, lsA2);
            lsA3 = fmaf(hidA, wv.w, lsA3);
            lsB0 = fmaf(hidB, wv.x, lsB0);
            lsB1 = fmaf(hidB, wv.y, lsB1);
            lsB2 = fmaf(hidB, wv.z, lsB2);
            lsB3 = fmaf(hidB, wv.w, lsB3);
        }

        // element A head
        {
            float s0 = softplus_(lsA2) + 0.001f;
            float s1 = softplus_(lsA3) + 0.001f;
            float y0 = yA0 + lsA0 + s0 * xa.x;
            float y1 = yA1 + lsA1 + s1 * xa.y;
            yA[t] = make_float2(y0, y1);
            pA0 *= s0; pA1 *= s1;
            yA0 = y0; yA1 = y1;
        }
        // element B head
        {
            float s0 = softplus_(lsB2) + 0.001f;
            float s1 = softplus_(lsB3) + 0.001f;
            float y0 = yB0 + lsB0 + s0 * xbv.x;
            float y1 = yB1 + lsB1 + s1 * xbv.y;
            if (vB) yB[t] = make_float2(y0, y1);
            pB0 *= s0; pB1 *= s1;
            yB0 = y0; yB1 = y1;
        }
    }

    // logabsdet (match reference: log|prod over T| summed over D)
    out[(size_t)Btot * (T_STEPS * 2) + b0] = logf(fabsf(pA0)) + logf(fabsf(pA1));
    if (vB)
        out[(size_t)Btot * (T_STEPS * 2) + b1r] = logf(fabsf(pB0)) + logf(fabsf(pB1));
}

extern "C" void kernel_launch(void* const* d_in, const int* in_sizes, int n_in,
                              void* d_out, int out_size)
{
    const float* x    = (const float*)d_in[0];
    const float* z    = (const float*)d_in[1];
    const float* W_ih = (const float*)d_in[2];
    const float* W_hh = (const float*)d_in[3];
    const float* b_ih = (const float*)d_in[4];
    const float* b_hh = (const float*)d_in[5];
    const float* W1   = (const float*)d_in[6];
    const float* b1   = (const float*)d_in[7];
    const float* W2   = (const float*)d_in[8];
    const float* b2   = (const float*)d_in[9];

    int B = in_sizes[1] / 64;   // z is (B, 64)
    int grid = (B + EPB - 1) / EPB;   // 293 for B=131072 -> waves 148+145 (99% balance)

    cudaFuncSetAttribute(flow_kernel, cudaFuncAttributeMaxDynamicSharedMemorySize, SMEM_BYTES);

    flow_kernel<<<grid, BLK, SMEM_BYTES>>>(
        x, z, W_ih, W_hh, b_ih, b_hh, W1, b1, W2, b2, (float*)d_out, B);
}

// round 9
// speedup vs baseline: 2.6592x; 2.3410x over previous
#include <cuda_runtime.h>
#include <cuda_fp16.h>
#include <cstdint>

#define T_STEPS 16
#define BLK 256
#define EPB 256            // 8 warps x 32 batch rows per warp

__device__ __forceinline__ float tanh_ap(float x) {
    float y; asm("tanh.approx.f32 %0, %1;" : "=f"(y) : "f"(x)); return y;
}
__device__ __forceinline__ float sigm(float x) {
    return fmaf(tanh_ap(0.5f * x), 0.5f, 0.5f);
}
__device__ __forceinline__ float softplus_(float x) {
    return fmaxf(x, 0.0f) + log1pf(__expf(-fabsf(x)));   // exact: sets rel_err
}
__device__ __forceinline__ unsigned packh2(float a, float b) {
    __half2 h = __floats2half2_rn(a, b);
    return *(unsigned*)&h;
}

// D = A(16x16 f16) @ B(16x8 f16) + C (f32), row.col
__device__ __forceinline__ void mma16816(float* c, const unsigned* a, const unsigned* b) {
    asm volatile("mma.sync.aligned.m16n8k16.row.col.f32.f16.f16.f32 "
                 "{%0,%1,%2,%3}, {%4,%5,%6,%7}, {%8,%9}, {%0,%1,%2,%3};"
                 : "+f"(c[0]), "+f"(c[1]), "+f"(c[2]), "+f"(c[3])
                 : "r"(a[0]), "r"(a[1]), "r"(a[2]), "r"(a[3]), "r"(b[0]), "r"(b[1]));
}

__global__ void __launch_bounds__(BLK)
flow_mma_kernel(const float* __restrict__ x, const float* __restrict__ z,
                const float* __restrict__ W_ih, const float* __restrict__ W_hh,
                const float* __restrict__ b_ih, const float* __restrict__ b_hh,
                const float* __restrict__ W1, const float* __restrict__ b1,
                const float* __restrict__ W2, const float* __restrict__ b2,
                float* __restrict__ out, int Btot)
{
    __shared__ __half whh_h[192 * 64];   // [j][k] row-major
    __shared__ __half w1t_h[32 * 64];    // [m][k] (W1 transposed)
    __shared__ __half w2t_h[8 * 32];     // [n][k] (W2 transposed, n padded to 8)
    __shared__ float4 giw_s[192];        // {wih0, wih1, bias, bhh_n}
    __shared__ float  b1_s[32];
    __shared__ float  b2_s[8];           // padded

    const int tid = threadIdx.x;

    // ---- stage weights (fp16) ----
    for (int i = tid; i < 12288; i += BLK) whh_h[i] = __float2half_rn(W_hh[i]);
    for (int i = tid; i < 2048; i += BLK) {
        int m = i >> 6, k = i & 63;
        w1t_h[i] = __float2half_rn(W1[k * 32 + m]);
    }
    for (int i = tid; i < 256; i += BLK) {
        int n = i >> 5, k = i & 31;
        w2t_h[i] = (n < 4) ? __float2half_rn(W2[k * 4 + n]) : __float2half_rn(0.0f);
    }
    for (int j = tid; j < 192; j += BLK) {
        float bi = b_ih[j], bh = b_hh[j];
        giw_s[j] = (j < 128) ? make_float4(W_ih[2 * j], W_ih[2 * j + 1], bi + bh, 0.0f)
                             : make_float4(W_ih[2 * j], W_ih[2 * j + 1], bi, bh);
    }
    if (tid < 32) b1_s[tid] = b1[tid];
    if (tid < 8)  b2_s[tid] = (tid < 4) ? b2[tid] : 0.0f;
    __syncthreads();

    const int wid = tid >> 5, lid = tid & 31;
    const int qr = lid >> 2, qc = lid & 3;
    const int rowbase = blockIdx.x * EPB + wid * 32;   // warp's first batch row
    const bool owner = (qc == 0);

    // ---- A fragments = h (init from z), [Mtile][ktile][reg], f16x2 ----
    unsigned A[2][4][4];
    #pragma unroll
    for (int mt = 0; mt < 2; ++mt)
        #pragma unroll
        for (int kt = 0; kt < 4; ++kt)
            #pragma unroll
            for (int rg = 0; rg < 4; ++rg) {
                int row = rowbase + 16 * mt + qr + 8 * (rg & 1);
                int k = 2 * qc + 8 * (rg >> 1) + 16 * kt;
                float2 v = *(const float2*)(z + (size_t)row * 64 + k);
                A[mt][kt][rg] = packh2(v.x, v.y);
            }

    // owner-lane per-row state: rows rowbase + qr + 8*yi, yi = 0..3
    float yown[8] = {0.f, 0.f, 0.f, 0.f, 0.f, 0.f, 0.f, 0.f};
    float pown[8] = {1.f, 1.f, 1.f, 1.f, 1.f, 1.f, 1.f, 1.f};

    #pragma unroll 1
    for (int t = 0; t < T_STEPS; ++t) {
        // broadcast y_prev of the 4 rows this lane epilogues (owner lane = 4*qr)
        float yp[8];
        #pragma unroll
        for (int yi = 0; yi < 4; ++yi) {
            yp[2 * yi]     = __shfl_sync(0xffffffffu, yown[2 * yi],     4 * qr);
            yp[2 * yi + 1] = __shfl_sync(0xffffffffu, yown[2 * yi + 1], 4 * qr);
        }
        // x_t for the quad's rows (same address across quad -> dedup'd)
        float2 xo[4];
        #pragma unroll
        for (int yi = 0; yi < 4; ++yi)
            xo[yi] = *(const float2*)(x + (size_t)(rowbase + qr + 8 * yi) * 32 + 2 * t);

        // ---- GRU: gh = h @ W_hh^T via HMMA, gates in epilogue ----
        unsigned Anew[2][4][4];
        #pragma unroll
        for (int jt = 0; jt < 8; ++jt) {
            float c[3][2][4];
            #pragma unroll
            for (int g = 0; g < 3; ++g)
                #pragma unroll
                for (int mt = 0; mt < 2; ++mt)
                    #pragma unroll
                    for (int i = 0; i < 4; ++i) c[g][mt][i] = 0.f;

            #pragma unroll
            for (int kt = 0; kt < 4; ++kt)
                #pragma unroll
                for (int g = 0; g < 3; ++g) {
                    int j = 8 * (jt + 8 * g) + qr;      // B col n = qr
                    unsigned b[2];
                    b[0] = *(const unsigned*)(whh_h + j * 64 + 16 * kt + 2 * qc);
                    b[1] = *(const unsigned*)(whh_h + j * 64 + 16 * kt + 2 * qc + 8);
                    mma16816(c[g][0], A[0][kt], b);
                    mma16816(c[g][1], A[1][kt], b);
                }

            const int j0 = 8 * jt + 2 * qc;
            const float4 gr0 = giw_s[j0],       gr1 = giw_s[j0 + 1];
            const float4 gz0 = giw_s[64 + j0],  gz1 = giw_s[64 + j0 + 1];
            const float4 gn0 = giw_s[128 + j0], gn1 = giw_s[128 + j0 + 1];

            #pragma unroll
            for (int mt = 0; mt < 2; ++mt)
                #pragma unroll
                for (int hf = 0; hf < 2; ++hf) {
                    const int yi = hf + 2 * mt;
                    const float y0 = yp[2 * yi], y1 = yp[2 * yi + 1];
                    // col 0
                    float r0 = sigm(fmaf(y1, gr0.y, fmaf(y0, gr0.x, gr0.z)) + c[0][mt][2 * hf]);
                    float u0 = sigm(fmaf(y1, gz0.y, fmaf(y0, gz0.x, gz0.z)) + c[1][mt][2 * hf]);
                    float n0 = tanh_ap(fmaf(r0, c[2][mt][2 * hf] + gn0.w,
                                            fmaf(y1, gn0.y, fmaf(y0, gn0.x, gn0.z))));
                    // col 1
                    float r1 = sigm(fmaf(y1, gr1.y, fmaf(y0, gr1.x, gr1.z)) + c[0][mt][2 * hf + 1]);
                    float u1 = sigm(fmaf(y1, gz1.y, fmaf(y0, gz1.x, gz1.z)) + c[1][mt][2 * hf + 1]);
                    float n1 = tanh_ap(fmaf(r1, c[2][mt][2 * hf + 1] + gn1.w,
                                            fmaf(y1, gn1.y, fmaf(y0, gn1.x, gn1.z))));
                    // hold = old h at same fragment slot
                    unsigned au = A[mt][jt >> 1][(jt & 1) * 2 + hf];
                    __half2 hh = *(__half2*)&au;
                    float h0 = fmaf(u0, __half2float(hh.x) - n0, n0);
                    float h1 = fmaf(u1, __half2float(hh.y) - n1, n1);
                    Anew[mt][jt >> 1][(jt & 1) * 2 + hf] = packh2(h0, h1);
                }
        }
        // commit h_new
        #pragma unroll
        for (int mt = 0; mt < 2; ++mt)
            #pragma unroll
            for (int kt = 0; kt < 4; ++kt)
                #pragma unroll
                for (int rg = 0; rg < 4; ++rg) A[mt][kt][rg] = Anew[mt][kt][rg];

        // ---- MLP1: hid = relu(h_new @ W1 + b1) via HMMA ----
        float ch[2][4][4];
        #pragma unroll
        for (int mt = 0; mt < 2; ++mt)
            #pragma unroll
            for (int nt = 0; nt < 4; ++nt)
                #pragma unroll
                for (int i = 0; i < 4; ++i) ch[mt][nt][i] = 0.f;
        #pragma unroll
        for (int kt = 0; kt < 4; ++kt)
            #pragma unroll
            for (int nt = 0; nt < 4; ++nt) {
                int m = 8 * nt + qr;
                unsigned b[2];
                b[0] = *(const unsigned*)(w1t_h + m * 64 + 16 * kt + 2 * qc);
                b[1] = *(const unsigned*)(w1t_h + m * 64 + 16 * kt + 2 * qc + 8);
                mma16816(ch[0][nt], A[0][kt], b);
                mma16816(ch[1][nt], A[1][kt], b);
            }
        // relu + bias, repack as A2 fragments (k = m)
        unsigned A2[2][2][4];
        #pragma unroll
        for (int nt = 0; nt < 4; ++nt) {
            float2 b1v = *(const float2*)(b1_s + 8 * nt + 2 * qc);
            #pragma unroll
            for (int mt = 0; mt < 2; ++mt)
                #pragma unroll
                for (int hf = 0; hf < 2; ++hf) {
                    float v0 = fmaxf(ch[mt][nt][2 * hf]     + b1v.x, 0.f);
                    float v1 = fmaxf(ch[mt][nt][2 * hf + 1] + b1v.y, 0.f);
                    A2[mt][nt >> 1][(nt & 1) * 2 + hf] = packh2(v0, v1);
                }
        }
        // ---- MLP2: ls = hid @ W2 + b2 (N padded to 8) ----
        float cl[2][4];
        #pragma unroll
        for (int mt = 0; mt < 2; ++mt)
            #pragma unroll
            for (int i = 0; i < 4; ++i) cl[mt][i] = 0.f;
        #pragma unroll
        for (int kt = 0; kt < 2; ++kt) {
            unsigned b[2];
            b[0] = *(const unsigned*)(w2t_h + qr * 32 + 16 * kt + 2 * qc);
            b[1] = *(const unsigned*)(w2t_h + qr * 32 + 16 * kt + 2 * qc + 8);
            mma16816(cl[0], A2[0][kt], b);
            mma16816(cl[1], A2[1][kt], b);
        }
        // head: qc==0 lanes hold (ls0,ls1)=dloc, qc==1 lanes hold (ls2,ls3)->scale
        float2 b2v = *(const float2*)(b2_s + 2 * qc);
        #pragma unroll
        for (int mt = 0; mt < 2; ++mt)
            #pragma unroll
            for (int hf = 0; hf < 2; ++hf) {
                const int yi = hf + 2 * mt;
                float v0 = cl[mt][2 * hf]     + b2v.x;
                float v1 = cl[mt][2 * hf + 1] + b2v.y;
                float sp0 = softplus_(v0) + 0.001f;
                float sp1 = softplus_(v1) + 0.001f;
                float s0 = __shfl_sync(0xffffffffu, sp0, (lid & ~3) | 1);
                float s1 = __shfl_sync(0xffffffffu, sp1, (lid & ~3) | 1);
                if (owner) {
                    float yn0 = yown[2 * yi]     + v0 + s0 * xo[yi].x;
                    float yn1 = yown[2 * yi + 1] + v1 + s1 * xo[yi].y;
                    yown[2 * yi] = yn0; yown[2 * yi + 1] = yn1;
                    pown[2 * yi] *= s0; pown[2 * yi + 1] *= s1;
                    int rowg = rowbase + qr + 8 * yi;
                    *(float2*)(out + (size_t)rowg * 32 + 2 * t) = make_float2(yn0, yn1);
                }
            }
    }

    if (owner) {
        #pragma unroll
        for (int yi = 0; yi < 4; ++yi) {
            int rowg = rowbase + qr + 8 * yi;
            out[(size_t)Btot * 32 + rowg] =
                logf(fabsf(pown[2 * yi])) + logf(fabsf(pown[2 * yi + 1]));
        }
    }
}

extern "C" void kernel_launch(void* const* d_in, const int* in_sizes, int n_in,
                              void* d_out, int out_size)
{
    const float* x    = (const float*)d_in[0];
    const float* z    = (const float*)d_in[1];
    const float* W_ih = (const float*)d_in[2];
    const float* W_hh = (const float*)d_in[3];
    const float* b_ih = (const float*)d_in[4];
    const float* b_hh = (const float*)d_in[5];
    const float* W1   = (const float*)d_in[6];
    const float* b1   = (const float*)d_in[7];
    const float* W2   = (const float*)d_in[8];
    const float* b2   = (const float*)d_in[9];

    int B = in_sizes[1] / 64;   // z is (B, 64)

    flow_mma_kernel<<<B / EPB, BLK>>>(
        x, z, W_ih, W_hh, b_ih, b_hh, W1, b1, W2, b2, (float*)d_out, B);
}